// round 9
// baseline (speedup 1.0000x reference)
#include <cuda_runtime.h>
#include <cuda_bf16.h>
#include <cstdint>
#include <type_traits>

#define N_NODES 50000
#define N_EDGES 800000
#define RELS 8
#define BASES 30
#define DIM 128
#define NR (RELS * DIM)   // 1024
#define SROW 152          // A-tile row stride (words); 152 mod 32 = 24 -> conflict-free
#define SMEM_BYTES (128 * SROW * 4)

// ---------------- scratch (device globals; no allocation allowed) ----------------
__device__ float g_W[DIM * NR];                     // W2[k][r*128+o]
__device__ uint2 g_fragL1[9][8192];                 // mma B-frags: 8 relations + root
__device__ uint2 g_fragL2[2][8192];                 // w_rel, w_root
__device__ float g_h[(size_t)N_NODES * DIM];        // layer-1 output
__device__ int   g_cnt2[N_NODES * RELS];
__device__ int   g_off2[N_NODES * RELS + 1];        // per-(node,rel) CSR offsets
__device__ int   g_cur2[N_NODES * RELS];
__device__ int   g_offn[N_NODES + 1];               // per-node CSR offsets
__device__ int   g_src[N_EDGES];                    // CSR-ordered src
__device__ float g_wt[N_EDGES];                     // CSR-ordered edge_norm

// ---------------- CSR build ----------------
__global__ void k_zero2() {
    int i = blockIdx.x * blockDim.x + threadIdx.x;
    if (i < N_NODES * RELS) g_cnt2[i] = 0;
}

__global__ void k_hist2(const int* __restrict__ ei, const int* __restrict__ et) {
    int e = blockIdx.x * blockDim.x + threadIdx.x;
    if (e < N_EDGES) {
        int dst = ei[N_EDGES + e];
        int rel = et[e];
        if ((unsigned)dst < N_NODES && (unsigned)rel < RELS)
            atomicAdd(&g_cnt2[dst * RELS + rel], 1);
    }
}

// single-block scan over node degrees; emits g_offn, g_off2, g_cur2
__global__ void k_scan2() {
    __shared__ int sw[32];
    int tid = threadIdx.x;
    int lane = tid & 31;
    int wid = tid >> 5;
    int carry = 0;
    for (int base = 0; base < N_NODES; base += 1024) {
        int i = base + tid;
        int c[8];
        int v = 0;
        if (i < N_NODES) {
            int4 a = *(const int4*)&g_cnt2[i * RELS];
            int4 b = *(const int4*)&g_cnt2[i * RELS + 4];
            c[0]=a.x; c[1]=a.y; c[2]=a.z; c[3]=a.w;
            c[4]=b.x; c[5]=b.y; c[6]=b.z; c[7]=b.w;
            #pragma unroll
            for (int r = 0; r < 8; r++) v += c[r];
        }
        int x = v;
        #pragma unroll
        for (int off = 1; off < 32; off <<= 1) {
            int t = __shfl_up_sync(0xffffffffu, x, off);
            if (lane >= off) x += t;
        }
        if (lane == 31) sw[wid] = x;
        __syncthreads();
        if (wid == 0) {
            int w = sw[lane];
            #pragma unroll
            for (int off = 1; off < 32; off <<= 1) {
                int t = __shfl_up_sync(0xffffffffu, w, off);
                if (lane >= off) w += t;
            }
            sw[lane] = w;
        }
        __syncthreads();
        int warp_off = (wid > 0) ? sw[wid - 1] : 0;
        int excl = carry + warp_off + x - v;
        if (i < N_NODES) {
            g_offn[i] = excl;
            int run = excl;
            #pragma unroll
            for (int r = 0; r < 8; r++) {
                g_off2[i * RELS + r] = run;
                g_cur2[i * RELS + r] = run;
                run += c[r];
            }
        }
        int total = sw[31];
        __syncthreads();
        carry += total;
    }
    if (tid == 0) { g_offn[N_NODES] = carry; g_off2[N_NODES * RELS] = carry; }
}

__global__ void k_scatter2(const int* __restrict__ ei, const int* __restrict__ et,
                           const float* __restrict__ norm) {
    int e = blockIdx.x * blockDim.x + threadIdx.x;
    if (e < N_EDGES) {
        int dst = ei[N_EDGES + e];
        int rel = et[e];
        if ((unsigned)dst < N_NODES && (unsigned)rel < RELS) {
            int src = ei[e];
            int p = atomicAdd(&g_cur2[dst * RELS + rel], 1);
            bool ok = (unsigned)src < N_NODES;
            g_src[p] = ok ? src : 0;
            g_wt[p]  = ok ? norm[e] : 0.f;
        }
    }
}

// ---------------- weights ----------------
// W2[k][r*128+o] = sum_b comp[r,b] * basis[b,k,o]
__global__ void k_W(const float* __restrict__ basis, const float* __restrict__ comp) {
    int idx = blockIdx.x * blockDim.x + threadIdx.x;
    if (idx >= RELS * DIM * DIM) return;
    int o = idx & (DIM - 1);
    int k = (idx >> 7) & (DIM - 1);
    int r = idx >> 14;
    float s = 0.f;
    #pragma unroll
    for (int b = 0; b < BASES; b++)
        s += comp[r * BASES + b] * basis[((size_t)b * DIM + k) * DIM + o];
    g_W[k * NR + r * DIM + o] = s;
}

__device__ __forceinline__ uint32_t f2tf(float f) {
    uint32_t u;
    asm volatile("cvt.rna.tf32.f32 %0, %1;" : "=r"(u) : "f"(f));
    return u;
}

// fragment layout: F[((kk8*4 + warp_n)*4 + nt)*32 + lane] =
//   { tf32(B[kk8*8+cq][n]), tf32(B[kk8*8+cq+4][n]) },  n = warp_n*32+nt*8+(lane>>2)
__global__ void k_fragL1(const float* __restrict__ root) {
    int idx = blockIdx.x * blockDim.x + threadIdx.x;   // 9*8192
    if (idx >= 9 * 8192) return;
    int m = idx >> 13;
    int rem = idx & 8191;
    int lane = rem & 31;
    int nt = (rem >> 5) & 3;
    int wn = (rem >> 7) & 3;
    int kk8 = rem >> 9;
    int rr = lane >> 2, cq = lane & 3;
    int n = wn * 32 + nt * 8 + rr;
    int k0 = kk8 * 8 + cq;
    float b0, b1;
    if (m < 8) { b0 = g_W[k0 * NR + m * DIM + n]; b1 = g_W[(k0 + 4) * NR + m * DIM + n]; }
    else       { b0 = root[k0 * DIM + n];         b1 = root[(k0 + 4) * DIM + n]; }
    g_fragL1[m][rem] = make_uint2(f2tf(b0), f2tf(b1));
}

__global__ void k_fragL2(const float* __restrict__ w_rel, const float* __restrict__ w_root) {
    int idx = blockIdx.x * blockDim.x + threadIdx.x;   // 2*8192
    if (idx >= 2 * 8192) return;
    int m = idx >> 13;
    int rem = idx & 8191;
    int lane = rem & 31;
    int nt = (rem >> 5) & 3;
    int wn = (rem >> 7) & 3;
    int kk8 = rem >> 9;
    int rr = lane >> 2, cq = lane & 3;
    int n = wn * 32 + nt * 8 + rr;
    int k0 = kk8 * 8 + cq;
    const float* B = m ? w_root : w_rel;
    g_fragL2[m][rem] = make_uint2(f2tf(B[k0 * DIM + n]), f2tf(B[(k0 + 4) * DIM + n]));
}

// ---------------- fused aggregate+GEMM layer ----------------
// L1: passes 0..7 gather x[src]*w over (dst,rel) sub-CSR; pass 8 = identity x.
//     out = g_h, bias = bias1.
// L2: pass 0 gathers g_h[src] over node CSR (weight 1); pass 1 = identity g_h.
//     out = param, bias = b_rel.
__device__ __forceinline__ void mma_tf32(float* c, const uint32_t* a, const uint32_t* b) {
    asm volatile(
        "mma.sync.aligned.m16n8k8.row.col.f32.tf32.tf32.f32 "
        "{%0,%1,%2,%3}, {%4,%5,%6,%7}, {%8,%9}, {%0,%1,%2,%3};"
        : "+f"(c[0]), "+f"(c[1]), "+f"(c[2]), "+f"(c[3])
        : "r"(a[0]), "r"(a[1]), "r"(a[2]), "r"(a[3]), "r"(b[0]), "r"(b[1]));
}

template<bool L1>
__global__ __launch_bounds__(256, 2)
void k_fused(const float* __restrict__ Xp, float* __restrict__ Cp,
             const float* __restrict__ bias)
{
    extern __shared__ __align__(16) uint32_t As[];   // [128][SROW]
    const float* X = L1 ? Xp : (const float*)g_h;
    float* C = L1 ? (float*)g_h : Cp;
    const int NPASS = L1 ? 9 : 2;

    int tid  = threadIdx.x;
    int lane = tid & 31;
    int wid  = tid >> 5;
    int warp_m = wid & 1;
    int warp_n = wid >> 1;
    int m0 = blockIdx.x * 128;
    int rr = lane >> 2;
    int cq = lane & 3;
    const int c4 = (lane & 3) * 4;                       // NOTE: per-lane col quad for FILL
    const int fill_g2 = lane >> 2;                       // 16-col group for fill
    const int s0 = (c4 & 8) | ((c4 >> 2) & 1);

    float acc[4][4][4];
    #pragma unroll
    for (int mt = 0; mt < 4; mt++)
        #pragma unroll
        for (int nt = 0; nt < 4; nt++)
            #pragma unroll
            for (int i = 0; i < 4; i++) acc[mt][nt][i] = 0.f;

    #pragma unroll 1
    for (int pass = 0; pass < NPASS; pass++) {
        bool identity = (pass == NPASS - 1);
        // ---- fill A tile: warp handles 16 rows, lane covers cols 4*lane..4*lane+3
        #pragma unroll 1
        for (int i = 0; i < 16; i++) {
            int row = wid * 16 + i;
            int node = m0 + row;
            float4 a = make_float4(0.f, 0.f, 0.f, 0.f);
            if (node < N_NODES) {
                if (identity) {
                    a = *(const float4*)&X[(size_t)node * DIM + 4 * lane];
                } else if (L1) {
                    int beg = g_off2[node * RELS + pass];
                    int end = g_off2[node * RELS + pass + 1];
                    for (int p = beg; p < end; p++) {
                        int s = g_src[p];
                        float w = g_wt[p];
                        float4 v = *(const float4*)&X[(size_t)s * DIM + 4 * lane];
                        a.x += w * v.x; a.y += w * v.y; a.z += w * v.z; a.w += w * v.w;
                    }
                } else {
                    int beg = g_offn[node], end = g_offn[node + 1];
                    for (int p = beg; p < end; p++) {
                        int s = g_src[p];
                        float4 v = *(const float4*)&X[(size_t)s * DIM + 4 * lane];
                        a.x += v.x; a.y += v.y; a.z += v.z; a.w += v.w;
                    }
                }
            }
            int base = row * SROW + fill_g2 * 16 + s0;
            As[base + 0] = f2tf(a.x);
            As[base + 2] = f2tf(a.y);
            As[base + 4] = f2tf(a.z);
            As[base + 6] = f2tf(a.w);
        }
        __syncthreads();

        // ---- MMA against this pass's B fragments
        const uint2* Fr = L1 ? g_fragL1[pass] : g_fragL2[pass];
        #pragma unroll
        for (int kk8 = 0; kk8 < 16; kk8++) {
            uint2 bf[4];
            #pragma unroll
            for (int nt = 0; nt < 4; nt++)
                bf[nt] = Fr[(((kk8 * 4 + warp_n) * 4 + nt) << 5) + lane];
            int g2 = kk8 >> 1;
            int kb = (kk8 & 1) * 8;
            uint2 alo[4], ahi[4];
            #pragma unroll
            for (int mt = 0; mt < 4; mt++) {
                int mb = warp_m * 64 + mt * 16;
                alo[mt] = *(const uint2*)&As[(mb + rr) * SROW + g2 * 16 + kb + 2 * cq];
                ahi[mt] = *(const uint2*)&As[(mb + rr + 8) * SROW + g2 * 16 + kb + 2 * cq];
            }
            #pragma unroll
            for (int mt = 0; mt < 4; mt++) {
                uint32_t a[4] = { alo[mt].x, ahi[mt].x, alo[mt].y, ahi[mt].y };
                #pragma unroll
                for (int nt = 0; nt < 4; nt++) {
                    uint32_t b[2] = { bf[nt].x, bf[nt].y };
                    mma_tf32(acc[mt][nt], a, b);
                }
            }
        }
        __syncthreads();
    }

    // ---- epilogue
    #pragma unroll
    for (int mt = 0; mt < 4; mt++) {
        int mA = m0 + warp_m * 64 + mt * 16 + rr;
        #pragma unroll
        for (int nt = 0; nt < 4; nt++) {
            int n = warp_n * 32 + nt * 8 + 2 * cq;
            if (mA < N_NODES) {
                float2 v = make_float2(acc[mt][nt][0] + bias[n], acc[mt][nt][1] + bias[n + 1]);
                *(float2*)&C[(size_t)mA * DIM + n] = v;
            }
            int mB = mA + 8;
            if (mB < N_NODES) {
                float2 v = make_float2(acc[mt][nt][2] + bias[n], acc[mt][nt][3] + bias[n + 1]);
                *(float2*)&C[(size_t)mB * DIM + n] = v;
            }
        }
    }
}

// ---------------- launch ----------------
extern "C" void kernel_launch(void* const* d_in, const int* in_sizes, int n_in,
                              void* d_out, int out_size)
{
    const float* x      = (const float*)d_in[0];
    const int*   ei     = (const int*)d_in[1];    // int64 in reference -> delivered as int32
    const int*   et     = (const int*)d_in[2];
    const float* norm   = (const float*)d_in[3];
    const float* basis  = (const float*)d_in[4];
    const float* comp   = (const float*)d_in[5];
    const float* root   = (const float*)d_in[6];
    const float* bias1  = (const float*)d_in[7];
    const float* w_rel  = (const float*)d_in[8];
    const float* b_rel  = (const float*)d_in[9];
    const float* w_root = (const float*)d_in[10];
    float* out = (float*)d_out;

    const int MBLK = (N_NODES + 127) / 128;   // 391

    static cudaStream_t s_side = nullptr;
    static cudaEvent_t ev_fork = nullptr, ev_join = nullptr;
    if (s_side == nullptr) {
        cudaStreamCreateWithFlags(&s_side, cudaStreamNonBlocking);
        cudaEventCreateWithFlags(&ev_fork, cudaEventDisableTiming);
        cudaEventCreateWithFlags(&ev_join, cudaEventDisableTiming);
        cudaFuncSetAttribute(k_fused<true>,  cudaFuncAttributeMaxDynamicSharedMemorySize, SMEM_BYTES);
        cudaFuncSetAttribute(k_fused<false>, cudaFuncAttributeMaxDynamicSharedMemorySize, SMEM_BYTES);
    }

    // ---- fork: CSR build on side stream ----
    cudaEventRecord(ev_fork, 0);
    cudaStreamWaitEvent(s_side, ev_fork, 0);
    k_zero2<<<(N_NODES * RELS + 255) / 256, 256, 0, s_side>>>();
    k_hist2<<<(N_EDGES + 255) / 256, 256, 0, s_side>>>(ei, et);
    k_scan2<<<1, 1024, 0, s_side>>>();
    k_scatter2<<<(N_EDGES + 255) / 256, 256, 0, s_side>>>(ei, et, norm);
    cudaEventRecord(ev_join, s_side);

    // ---- main: weights + fragment prep ----
    k_W<<<(RELS * DIM * DIM + 255) / 256, 256>>>(basis, comp);
    k_fragL1<<<(9 * 8192 + 255) / 256, 256>>>(root);
    k_fragL2<<<(2 * 8192 + 255) / 256, 256>>>(w_rel, w_root);

    // ---- join, then fused layers ----
    cudaStreamWaitEvent(0, ev_join, 0);
    k_fused<true><<<MBLK, 256, SMEM_BYTES>>>(x, nullptr, bias1);
    k_fused<false><<<MBLK, 256, SMEM_BYTES>>>(nullptr, out, b_rel);
}

// round 10
// speedup vs baseline: 1.1282x; 1.1282x over previous
#include <cuda_runtime.h>
#include <cuda_bf16.h>
#include <cstdint>
#include <type_traits>

#define N_NODES 50000
#define N_EDGES 800000
#define RELS 8
#define BASES 30
#define DIM 128
#define NR (RELS * DIM)   // 1024

// ---------------- scratch (device globals; no allocation allowed) ----------------
__device__ float g_W[NR * DIM];                     // W2cat[(r*128+k)][o]
__device__ float g_aggx[(size_t)N_NODES * NR];      // [N,8,128] per-relation aggregates
__device__ float g_h[(size_t)N_NODES * DIM];        // layer-1 output
__device__ float g_agg2[(size_t)N_NODES * DIM];     // layer-2 aggregate
__device__ int   g_cnt2[N_NODES * RELS];
__device__ int   g_off2[N_NODES * RELS + 1];        // per-(node,rel) CSR offsets
__device__ int   g_cur2[N_NODES * RELS];
__device__ int   g_offn[N_NODES + 1];               // per-node CSR offsets
__device__ int   g_src[N_EDGES];                    // CSR-ordered src
__device__ float g_wt[N_EDGES];                     // CSR-ordered edge_norm

// ---------------- CSR build (verified in R9) ----------------
__global__ void k_zero2() {
    int i = blockIdx.x * blockDim.x + threadIdx.x;
    if (i < N_NODES * RELS) g_cnt2[i] = 0;
}

__global__ void k_hist2(const int* __restrict__ ei, const int* __restrict__ et) {
    int e = blockIdx.x * blockDim.x + threadIdx.x;
    if (e < N_EDGES) {
        int dst = ei[N_EDGES + e];
        int rel = et[e];
        if ((unsigned)dst < N_NODES && (unsigned)rel < RELS)
            atomicAdd(&g_cnt2[dst * RELS + rel], 1);
    }
}

__global__ void k_scan2() {
    __shared__ int sw[32];
    int tid = threadIdx.x;
    int lane = tid & 31;
    int wid = tid >> 5;
    int carry = 0;
    for (int base = 0; base < N_NODES; base += 1024) {
        int i = base + tid;
        int c[8];
        int v = 0;
        if (i < N_NODES) {
            int4 a = *(const int4*)&g_cnt2[i * RELS];
            int4 b = *(const int4*)&g_cnt2[i * RELS + 4];
            c[0]=a.x; c[1]=a.y; c[2]=a.z; c[3]=a.w;
            c[4]=b.x; c[5]=b.y; c[6]=b.z; c[7]=b.w;
            #pragma unroll
            for (int r = 0; r < 8; r++) v += c[r];
        }
        int x = v;
        #pragma unroll
        for (int off = 1; off < 32; off <<= 1) {
            int t = __shfl_up_sync(0xffffffffu, x, off);
            if (lane >= off) x += t;
        }
        if (lane == 31) sw[wid] = x;
        __syncthreads();
        if (wid == 0) {
            int w = sw[lane];
            #pragma unroll
            for (int off = 1; off < 32; off <<= 1) {
                int t = __shfl_up_sync(0xffffffffu, w, off);
                if (lane >= off) w += t;
            }
            sw[lane] = w;
        }
        __syncthreads();
        int warp_off = (wid > 0) ? sw[wid - 1] : 0;
        int excl = carry + warp_off + x - v;
        if (i < N_NODES) {
            g_offn[i] = excl;
            int run = excl;
            #pragma unroll
            for (int r = 0; r < 8; r++) {
                g_off2[i * RELS + r] = run;
                g_cur2[i * RELS + r] = run;
                run += c[r];
            }
        }
        int total = sw[31];
        __syncthreads();
        carry += total;
    }
    if (tid == 0) { g_offn[N_NODES] = carry; g_off2[N_NODES * RELS] = carry; }
}

__global__ void k_scatter2(const int* __restrict__ ei, const int* __restrict__ et,
                           const float* __restrict__ norm) {
    int e = blockIdx.x * blockDim.x + threadIdx.x;
    if (e < N_EDGES) {
        int dst = ei[N_EDGES + e];
        int rel = et[e];
        if ((unsigned)dst < N_NODES && (unsigned)rel < RELS) {
            int src = ei[e];
            int p = atomicAdd(&g_cur2[dst * RELS + rel], 1);
            bool ok = (unsigned)src < N_NODES;
            g_src[p] = ok ? src : 0;
            g_wt[p]  = ok ? norm[e] : 0.f;
        }
    }
}

// ---------------- weights: W2cat[(r*128+k)][o] = sum_b comp[r,b]*basis[b,k,o] ----
__global__ void k_W(const float* __restrict__ basis, const float* __restrict__ comp) {
    int idx = blockIdx.x * blockDim.x + threadIdx.x;
    if (idx >= RELS * DIM * DIM) return;
    int o = idx & (DIM - 1);
    int k = (idx >> 7) & (DIM - 1);
    int r = idx >> 14;
    float s = 0.f;
    #pragma unroll
    for (int b = 0; b < BASES; b++)
        s += comp[r * BASES + b] * basis[((size_t)b * DIM + k) * DIM + o];
    g_W[idx] = s;   // idx == (r*128+k)*128 + o
}

// ---------------- per-relation aggregation of raw x (warp per node) ----------------
// g_aggx[n, r, :] = sum_{p in sub-CSR(n,r)} w_p * x[src_p, :]
__global__ void k_aggX(const float* __restrict__ x)
{
    int n = blockIdx.x * (blockDim.x >> 5) + (threadIdx.x >> 5);
    if (n >= N_NODES) return;
    int lane = threadIdx.x & 31;
    #pragma unroll 1
    for (int r = 0; r < RELS; r++) {
        int beg = g_off2[n * RELS + r], end = g_off2[n * RELS + r + 1];
        float4 acc = make_float4(0.f, 0.f, 0.f, 0.f);
        for (int p = beg; p < end; p++) {
            int s = g_src[p];
            float w = g_wt[p];
            float4 v = *((const float4*)(x + (size_t)s * DIM) + lane);
            acc.x += w * v.x; acc.y += w * v.y; acc.z += w * v.z; acc.w += w * v.w;
        }
        *((float4*)(g_aggx + (size_t)n * NR + r * DIM) + lane) = acc;
    }
}

// layer 2: g_agg2[n] = sum_{p in CSR[n]} g_h[src_p, :]
__global__ void k_agg2()
{
    int n = blockIdx.x * (blockDim.x >> 5) + (threadIdx.x >> 5);
    if (n >= N_NODES) return;
    int lane = threadIdx.x & 31;
    int beg = g_offn[n], end = g_offn[n + 1];
    float4 acc = make_float4(0.f, 0.f, 0.f, 0.f);
    for (int p = beg; p < end; p++) {
        int src = g_src[p];
        float4 v = *((const float4*)(g_h + (size_t)src * DIM) + lane);
        acc.x += v.x; acc.y += v.y; acc.z += v.z; acc.w += v.w;
    }
    *((float4*)(g_agg2 + (size_t)n * DIM) + lane) = acc;
}

// ---------------- tf32 tensor-core GEMM (R8-proven) ----------------
// C[M,N] (+)= A[M,K] @ B[K,N] (+bias), fp32 accumulate, tf32(rna) inputs.
// 128x128 block, 256 threads = 8 warps (2m x 4n), warp 64x32, 4x4 m16n8k8.
// LDG_chunk's argument is an ELEMENT k-offset (multiple of 16).
// AMODE: 3=concat[g_agg2|g_h] (KT=256), 4=concat[g_aggx|Ap(x)] (KT=1152)
// BMODE: 2=concat[Bp|Bp2] (KT=256), 3=concat[g_W|Bp2(root)] (KT=1152)
// CMODE: 0=param, 2=g_h

__device__ __forceinline__ uint32_t f2tf(float f) {
    uint32_t u;
    asm volatile("cvt.rna.tf32.f32 %0, %1;" : "=r"(u) : "f"(f));
    return u;
}

__device__ __forceinline__ void mma_tf32(float* c, const uint32_t* a, const uint32_t* b) {
    asm volatile(
        "mma.sync.aligned.m16n8k8.row.col.f32.tf32.tf32.f32 "
        "{%0,%1,%2,%3}, {%4,%5,%6,%7}, {%8,%9}, {%0,%1,%2,%3};"
        : "+f"(c[0]), "+f"(c[1]), "+f"(c[2]), "+f"(c[3])
        : "r"(a[0]), "r"(a[1]), "r"(a[2]), "r"(a[3]), "r"(b[0]), "r"(b[1]));
}

template<int KT, int AMODE, int BMODE, int CMODE, bool ADD_C, bool HAS_BIAS>
__global__ __launch_bounds__(256, 2)
void k_gemm_tc(const float* __restrict__ Ap, const float* __restrict__ Bp,
               const float* __restrict__ Bp2, float* __restrict__ Cp,
               int M, int N, const float* __restrict__ bias)
{
    __shared__ __align__(16) uint32_t As[2][128][24];
    __shared__ __align__(16) uint32_t Bs[2][16][136];

    int tid  = threadIdx.x;
    int lane = tid & 31;
    int wid  = tid >> 5;
    int warp_m = wid & 1;
    int warp_n = wid >> 1;
    int m0 = blockIdx.y * 128;
    int n0 = blockIdx.x * 128;
    int r  = lane >> 2;
    int cq = lane & 3;

    float acc[4][4][4];
    #pragma unroll
    for (int mt = 0; mt < 4; mt++)
        #pragma unroll
        for (int nt = 0; nt < 4; nt++)
            #pragma unroll
            for (int i = 0; i < 4; i++) acc[mt][nt][i] = 0.f;

    float4 aReg[2], bReg[2];

    const int fa_m  = tid >> 2;          // A: row within tile (0..63, +64 for l=1)
    const int fa_c4 = (tid & 3) * 4;     // A: k-quad base
    const int fa_s0 = (fa_c4 & 8) | ((fa_c4 >> 2) & 1);   // interleave slot base

    auto LDG_chunk = [&](int k0) {       // k0 = element offset in K, multiple of 16
        const float* Asrc; int astride; int acol;
        if (AMODE == 3) {
            Asrc = (k0 < DIM) ? (const float*)g_agg2 : (const float*)g_h;
            acol = k0 & (DIM - 1); astride = DIM;
        } else if (AMODE == 4) {
            if (k0 < NR) { Asrc = (const float*)g_aggx; acol = k0; astride = NR; }
            else         { Asrc = Ap; acol = k0 - NR; astride = DIM; }
        } else { Asrc = Ap; acol = k0; astride = KT; }
        #pragma unroll
        for (int l = 0; l < 2; l++) {
            int gm = m0 + fa_m + l * 64;
            aReg[l] = (gm < M) ? *(const float4*)&Asrc[(size_t)gm * astride + acol + fa_c4]
                               : make_float4(0.f, 0.f, 0.f, 0.f);
        }
        const float* Bsrc; int brow;
        if (BMODE == 2)      { Bsrc = (k0 < DIM) ? Bp : Bp2; brow = k0 & (DIM - 1); }
        else if (BMODE == 3) { if (k0 < NR) { Bsrc = (const float*)g_W; brow = k0; }
                               else         { Bsrc = Bp2; brow = k0 - NR; } }
        else { Bsrc = Bp; brow = k0; }
        #pragma unroll
        for (int l = 0; l < 2; l++) {
            int idx = tid + l * 256;
            int kr = idx >> 5;
            int c = (idx & 31) * 4;
            bReg[l] = *(const float4*)&Bsrc[(size_t)(brow + kr) * N + n0 + c];
        }
    };

    auto STS_chunk = [&](auto bufc) {
        constexpr int buf = decltype(bufc)::value;
        #pragma unroll
        for (int l = 0; l < 2; l++) {
            int m = fa_m + l * 64;
            As[buf][m][fa_s0 + 0] = f2tf(aReg[l].x);
            As[buf][m][fa_s0 + 2] = f2tf(aReg[l].y);
            As[buf][m][fa_s0 + 4] = f2tf(aReg[l].z);
            As[buf][m][fa_s0 + 6] = f2tf(aReg[l].w);
        }
        #pragma unroll
        for (int l = 0; l < 2; l++) {
            int idx = tid + l * 256;
            int kr = idx >> 5;
            int c = (idx & 31) * 4;
            *(uint4*)&Bs[buf][kr][c] =
                make_uint4(f2tf(bReg[l].x), f2tf(bReg[l].y), f2tf(bReg[l].z), f2tf(bReg[l].w));
        }
    };

    auto MMA_chunk = [&](auto bufc) {
        constexpr int buf = decltype(bufc)::value;
        #pragma unroll
        for (int kk = 0; kk < 16; kk += 8) {
            uint32_t afr[4][4], bfr[4][2];
            #pragma unroll
            for (int mt = 0; mt < 4; mt++) {
                int mb = warp_m * 64 + mt * 16;
                uint2 lo = *(const uint2*)&As[buf][mb + r][kk + 2 * cq];
                uint2 hi = *(const uint2*)&As[buf][mb + r + 8][kk + 2 * cq];
                afr[mt][0] = lo.x; afr[mt][1] = hi.x;
                afr[mt][2] = lo.y; afr[mt][3] = hi.y;
            }
            #pragma unroll
            for (int nt = 0; nt < 4; nt++) {
                int nb = warp_n * 32 + nt * 8;
                bfr[nt][0] = Bs[buf][kk + cq][nb + r];
                bfr[nt][1] = Bs[buf][kk + cq + 4][nb + r];
            }
            #pragma unroll
            for (int mt = 0; mt < 4; mt++)
                #pragma unroll
                for (int nt = 0; nt < 4; nt++)
                    mma_tf32(acc[mt][nt], afr[mt], bfr[nt]);
        }
    };

    std::integral_constant<int, 0> B0;
    std::integral_constant<int, 1> B1;

    const int NC = KT / 16;     // even
    LDG_chunk(0);
    STS_chunk(B0);
    __syncthreads();
    #pragma unroll 1
    for (int c = 0; c < NC; c += 2) {
        LDG_chunk((c + 1) * 16);
        MMA_chunk(B0);
        STS_chunk(B1);
        __syncthreads();
        if (c + 2 < NC) LDG_chunk((c + 2) * 16);
        MMA_chunk(B1);
        if (c + 2 < NC) {
            STS_chunk(B0);
            __syncthreads();
        }
    }

    float* C = (CMODE == 0) ? Cp : g_h;
    #pragma unroll
    for (int mt = 0; mt < 4; mt++) {
        int mA = m0 + warp_m * 64 + mt * 16 + r;
        #pragma unroll
        for (int nt = 0; nt < 4; nt++) {
            int n = n0 + warp_n * 32 + nt * 8 + 2 * cq;
            if (mA < M) {
                float2 v = make_float2(acc[mt][nt][0], acc[mt][nt][1]);
                if (HAS_BIAS) { v.x += bias[n]; v.y += bias[n + 1]; }
                if (ADD_C) {
                    float2 o = *(const float2*)&C[(size_t)mA * N + n];
                    v.x += o.x; v.y += o.y;
                }
                *(float2*)&C[(size_t)mA * N + n] = v;
            }
            int mB = mA + 8;
            if (mB < M) {
                float2 v = make_float2(acc[mt][nt][2], acc[mt][nt][3]);
                if (HAS_BIAS) { v.x += bias[n]; v.y += bias[n + 1]; }
                if (ADD_C) {
                    float2 o = *(const float2*)&C[(size_t)mB * N + n];
                    v.x += o.x; v.y += o.y;
                }
                *(float2*)&C[(size_t)mB * N + n] = v;
            }
        }
    }
}

// ---------------- launch ----------------
extern "C" void kernel_launch(void* const* d_in, const int* in_sizes, int n_in,
                              void* d_out, int out_size)
{
    const float* x      = (const float*)d_in[0];
    const int*   ei     = (const int*)d_in[1];    // int64 in reference -> delivered as int32
    const int*   et     = (const int*)d_in[2];
    const float* norm   = (const float*)d_in[3];
    const float* basis  = (const float*)d_in[4];
    const float* comp   = (const float*)d_in[5];
    const float* root   = (const float*)d_in[6];
    const float* bias1  = (const float*)d_in[7];
    const float* w_rel  = (const float*)d_in[8];
    const float* b_rel  = (const float*)d_in[9];
    const float* w_root = (const float*)d_in[10];
    float* out = (float*)d_out;

    const int MBLK = (N_NODES + 127) / 128;   // 391

    static cudaStream_t s_side = nullptr;
    static cudaEvent_t ev_fork = nullptr, ev_join = nullptr;
    if (s_side == nullptr) {
        cudaStreamCreateWithFlags(&s_side, cudaStreamNonBlocking);
        cudaEventCreateWithFlags(&ev_fork, cudaEventDisableTiming);
        cudaEventCreateWithFlags(&ev_join, cudaEventDisableTiming);
    }

    // ---- fork: weights on side stream, CSR build on main (critical path) ----
    cudaEventRecord(ev_fork, 0);
    cudaStreamWaitEvent(s_side, ev_fork, 0);
    k_W<<<(RELS * DIM * DIM + 255) / 256, 256, 0, s_side>>>(basis, comp);
    cudaEventRecord(ev_join, s_side);

    k_zero2<<<(N_NODES * RELS + 255) / 256, 256>>>();
    k_hist2<<<(N_EDGES + 255) / 256, 256>>>(ei, et);
    k_scan2<<<1, 1024>>>();
    k_scatter2<<<(N_EDGES + 255) / 256, 256>>>(ei, et, norm);

    // per-relation aggregation of raw x (x is L2-resident)
    k_aggX<<<(N_NODES + 7) / 8, 256>>>(x);

    cudaStreamWaitEvent(0, ev_join, 0);
    // layer 1 in ONE concat GEMM: h = [aggX | x] @ [W2cat; root] + bias1, K=1152
    {
        dim3 grid(1, MBLK);
        k_gemm_tc<1152, 4, 3, 2, false, true><<<grid, 256>>>(x, nullptr, root, nullptr,
                                                             N_NODES, DIM, bias1);
    }
    // layer-2 aggregation -> g_agg2 (g_h is L2-resident)
    k_agg2<<<(N_NODES + 7) / 8, 256>>>();
    // out = [agg2, h] @ [w_rel; w_root] + b_rel   (fused K=256)
    {
        dim3 grid(1, MBLK);
        k_gemm_tc<256, 3, 2, 0, false, true><<<grid, 256>>>(nullptr, w_rel, w_root, out,
                                                            N_NODES, DIM, b_rel);
    }
}

// round 11
// speedup vs baseline: 2.7134x; 2.4051x over previous
#include <cuda_runtime.h>
#include <cuda_bf16.h>
#include <cstdint>
#include <type_traits>

#define N_NODES 50000
#define N_EDGES 800000
#define RELS 8
#define BASES 30
#define DIM 128
#define NR (RELS * DIM)   // 1024
#define SCAN_B 512
#define SCAN_G ((N_NODES + SCAN_B - 1) / SCAN_B)   // 98

// ---------------- scratch (device globals; no allocation allowed) ----------------
__device__ float g_W[NR * DIM];                     // W2cat[(r*128+k)][o]
__device__ float g_aggx[(size_t)N_NODES * NR];      // [N,8,128] per-relation aggregates
__device__ float g_h[(size_t)N_NODES * DIM];        // layer-1 output
__device__ float g_agg2[(size_t)N_NODES * DIM];     // layer-2 aggregate
__device__ int   g_cnt2[N_NODES * RELS];
__device__ int   g_off2[N_NODES * RELS + 1];        // per-(node,rel) CSR offsets
__device__ int   g_cur2[N_NODES * RELS];
__device__ int   g_offn[N_NODES + 1];               // per-node CSR offsets
__device__ int   g_bsum[SCAN_G];                    // per-block scan totals
__device__ int   g_boff[SCAN_G + 1];                // block offsets
__device__ int   g_src[N_EDGES];                    // CSR-ordered src
__device__ float g_wt[N_EDGES];                     // CSR-ordered edge_norm

// ---------------- CSR build ----------------
__global__ void k_zero2() {
    int i = blockIdx.x * blockDim.x + threadIdx.x;
    if (i < N_NODES * RELS) g_cnt2[i] = 0;
}

__global__ void k_hist2(const int* __restrict__ ei, const int* __restrict__ et) {
    int e = blockIdx.x * blockDim.x + threadIdx.x;
    if (e < N_EDGES) {
        int dst = ei[N_EDGES + e];
        int rel = et[e];
        if ((unsigned)dst < N_NODES && (unsigned)rel < RELS)
            atomicAdd(&g_cnt2[dst * RELS + rel], 1);
    }
}

// scan phase 1: per-block exclusive scan of node degree totals
__global__ void k_scan_p1() {
    __shared__ int sw[16];
    int t = threadIdx.x;                 // 0..511
    int i = blockIdx.x * SCAN_B + t;
    int lane = t & 31, wid = t >> 5;     // 16 warps
    int v = 0;
    if (i < N_NODES) {
        int4 a = *(const int4*)&g_cnt2[i * RELS];
        int4 b = *(const int4*)&g_cnt2[i * RELS + 4];
        v = a.x + a.y + a.z + a.w + b.x + b.y + b.z + b.w;
    }
    int x = v;
    #pragma unroll
    for (int off = 1; off < 32; off <<= 1) {
        int s = __shfl_up_sync(0xffffffffu, x, off);
        if (lane >= off) x += s;
    }
    if (lane == 31) sw[wid] = x;
    __syncthreads();
    if (wid == 0 && lane < 16) {
        int w = sw[lane];
        #pragma unroll
        for (int off = 1; off < 16; off <<= 1) {
            int s = __shfl_up_sync(0xffffu, w, off);
            if (lane >= off) w += s;
        }
        sw[lane] = w;
    }
    __syncthreads();
    int warp_off = (wid > 0) ? sw[wid - 1] : 0;
    if (i < N_NODES) g_offn[i] = warp_off + x - v;   // within-block exclusive
    if (t == SCAN_B - 1) g_bsum[blockIdx.x] = sw[15];
}

// scan phase 2: single small block scans the block totals
__global__ void k_scan_p2() {
    __shared__ int sb[SCAN_G];
    int t = threadIdx.x;                 // 128 threads
    for (int j = t; j < SCAN_G; j += blockDim.x) sb[j] = g_bsum[j];
    __syncthreads();
    if (t == 0) {
        int run = 0;
        for (int j = 0; j < SCAN_G; j++) { g_boff[j] = run; run += sb[j]; }
        g_boff[SCAN_G] = run;
        g_offn[N_NODES] = run;
        g_off2[N_NODES * RELS] = run;
    }
}

// scan phase 3: add block offsets, expand per-relation sub-offsets
__global__ void k_scan_p3() {
    int i = blockIdx.x * SCAN_B + threadIdx.x;
    if (i >= N_NODES) return;
    int ex = g_offn[i] + g_boff[blockIdx.x];
    int4 a = *(const int4*)&g_cnt2[i * RELS];
    int4 b = *(const int4*)&g_cnt2[i * RELS + 4];
    int c[8] = { a.x, a.y, a.z, a.w, b.x, b.y, b.z, b.w };
    g_offn[i] = ex;
    int run = ex;
    #pragma unroll
    for (int r = 0; r < 8; r++) {
        g_off2[i * RELS + r] = run;
        g_cur2[i * RELS + r] = run;
        run += c[r];
    }
}

__global__ void k_scatter2(const int* __restrict__ ei, const int* __restrict__ et,
                           const float* __restrict__ norm) {
    int e = blockIdx.x * blockDim.x + threadIdx.x;
    if (e < N_EDGES) {
        int dst = ei[N_EDGES + e];
        int rel = et[e];
        if ((unsigned)dst < N_NODES && (unsigned)rel < RELS) {
            int src = ei[e];
            int p = atomicAdd(&g_cur2[dst * RELS + rel], 1);
            bool ok = (unsigned)src < N_NODES;
            g_src[p] = ok ? src : 0;
            g_wt[p]  = ok ? norm[e] : 0.f;
        }
    }
}

// ---------------- weights: W2cat[(r*128+k)][o] = sum_b comp[r,b]*basis[b,k,o] ----
__global__ void k_W(const float* __restrict__ basis, const float* __restrict__ comp) {
    int idx = blockIdx.x * blockDim.x + threadIdx.x;
    if (idx >= RELS * DIM * DIM) return;
    int o = idx & (DIM - 1);
    int k = (idx >> 7) & (DIM - 1);
    int r = idx >> 14;
    float s = 0.f;
    #pragma unroll
    for (int b = 0; b < BASES; b++)
        s += comp[r * BASES + b] * basis[((size_t)b * DIM + k) * DIM + o];
    g_W[idx] = s;   // idx == (r*128+k)*128 + o
}

// ---------------- per-relation aggregation of raw x (warp per node) ----------------
__global__ void k_aggX(const float* __restrict__ x)
{
    int n = blockIdx.x * (blockDim.x >> 5) + (threadIdx.x >> 5);
    if (n >= N_NODES) return;
    int lane = threadIdx.x & 31;
    #pragma unroll 1
    for (int r = 0; r < RELS; r++) {
        int beg = g_off2[n * RELS + r], end = g_off2[n * RELS + r + 1];
        float4 acc = make_float4(0.f, 0.f, 0.f, 0.f);
        for (int p = beg; p < end; p++) {
            int s = g_src[p];
            float w = g_wt[p];
            float4 v = *((const float4*)(x + (size_t)s * DIM) + lane);
            acc.x += w * v.x; acc.y += w * v.y; acc.z += w * v.z; acc.w += w * v.w;
        }
        *((float4*)(g_aggx + (size_t)n * NR + r * DIM) + lane) = acc;
    }
}

// layer 2: g_agg2[n] = sum_{p in CSR[n]} g_h[src_p, :]
__global__ void k_agg2()
{
    int n = blockIdx.x * (blockDim.x >> 5) + (threadIdx.x >> 5);
    if (n >= N_NODES) return;
    int lane = threadIdx.x & 31;
    int beg = g_offn[n], end = g_offn[n + 1];
    float4 acc = make_float4(0.f, 0.f, 0.f, 0.f);
    for (int p = beg; p < end; p++) {
        int src = g_src[p];
        float4 v = *((const float4*)(g_h + (size_t)src * DIM) + lane);
        acc.x += v.x; acc.y += v.y; acc.z += v.z; acc.w += v.w;
    }
    *((float4*)(g_agg2 + (size_t)n * DIM) + lane) = acc;
}

// ---------------- tf32 tensor-core GEMM (R8-proven) ----------------
// C[M,N] (+)= A[M,K] @ B[K,N] (+bias), fp32 accumulate, tf32(rna) inputs.
// 128x128 block, 256 threads = 8 warps (2m x 4n), warp 64x32, 4x4 m16n8k8.
// LDG_chunk's argument is an ELEMENT k-offset (multiple of 16).
// AMODE: 3=concat[g_agg2|g_h] (KT=256), 4=concat[g_aggx|Ap(x)] (KT=1152)
// BMODE: 2=concat[Bp|Bp2] (KT=256), 3=concat[g_W|Bp2(root)] (KT=1152)
// CMODE: 0=param, 2=g_h

__device__ __forceinline__ uint32_t f2tf(float f) {
    uint32_t u;
    asm volatile("cvt.rna.tf32.f32 %0, %1;" : "=r"(u) : "f"(f));
    return u;
}

__device__ __forceinline__ void mma_tf32(float* c, const uint32_t* a, const uint32_t* b) {
    asm volatile(
        "mma.sync.aligned.m16n8k8.row.col.f32.tf32.tf32.f32 "
        "{%0,%1,%2,%3}, {%4,%5,%6,%7}, {%8,%9}, {%0,%1,%2,%3};"
        : "+f"(c[0]), "+f"(c[1]), "+f"(c[2]), "+f"(c[3])
        : "r"(a[0]), "r"(a[1]), "r"(a[2]), "r"(a[3]), "r"(b[0]), "r"(b[1]));
}

template<int KT, int AMODE, int BMODE, int CMODE, bool ADD_C, bool HAS_BIAS>
__global__ __launch_bounds__(256, 2)
void k_gemm_tc(const float* __restrict__ Ap, const float* __restrict__ Bp,
               const float* __restrict__ Bp2, float* __restrict__ Cp,
               int M, int N, const float* __restrict__ bias)
{
    __shared__ __align__(16) uint32_t As[2][128][24];
    __shared__ __align__(16) uint32_t Bs[2][16][136];

    int tid  = threadIdx.x;
    int lane = tid & 31;
    int wid  = tid >> 5;
    int warp_m = wid & 1;
    int warp_n = wid >> 1;
    int m0 = blockIdx.y * 128;
    int n0 = blockIdx.x * 128;
    int r  = lane >> 2;
    int cq = lane & 3;

    float acc[4][4][4];
    #pragma unroll
    for (int mt = 0; mt < 4; mt++)
        #pragma unroll
        for (int nt = 0; nt < 4; nt++)
            #pragma unroll
            for (int i = 0; i < 4; i++) acc[mt][nt][i] = 0.f;

    float4 aReg[2], bReg[2];

    const int fa_m  = tid >> 2;          // A: row within tile (0..63, +64 for l=1)
    const int fa_c4 = (tid & 3) * 4;     // A: k-quad base
    const int fa_s0 = (fa_c4 & 8) | ((fa_c4 >> 2) & 1);   // interleave slot base

    auto LDG_chunk = [&](int k0) {       // k0 = element offset in K, multiple of 16
        const float* Asrc; int astride; int acol;
        if (AMODE == 3) {
            Asrc = (k0 < DIM) ? (const float*)g_agg2 : (const float*)g_h;
            acol = k0 & (DIM - 1); astride = DIM;
        } else if (AMODE == 4) {
            if (k0 < NR) { Asrc = (const float*)g_aggx; acol = k0; astride = NR; }
            else         { Asrc = Ap; acol = k0 - NR; astride = DIM; }
        } else { Asrc = Ap; acol = k0; astride = KT; }
        #pragma unroll
        for (int l = 0; l < 2; l++) {
            int gm = m0 + fa_m + l * 64;
            aReg[l] = (gm < M) ? *(const float4*)&Asrc[(size_t)gm * astride + acol + fa_c4]
                               : make_float4(0.f, 0.f, 0.f, 0.f);
        }
        const float* Bsrc; int brow;
        if (BMODE == 2)      { Bsrc = (k0 < DIM) ? Bp : Bp2; brow = k0 & (DIM - 1); }
        else if (BMODE == 3) { if (k0 < NR) { Bsrc = (const float*)g_W; brow = k0; }
                               else         { Bsrc = Bp2; brow = k0 - NR; } }
        else { Bsrc = Bp; brow = k0; }
        #pragma unroll
        for (int l = 0; l < 2; l++) {
            int idx = tid + l * 256;
            int kr = idx >> 5;
            int c = (idx & 31) * 4;
            bReg[l] = *(const float4*)&Bsrc[(size_t)(brow + kr) * N + n0 + c];
        }
    };

    auto STS_chunk = [&](auto bufc) {
        constexpr int buf = decltype(bufc)::value;
        #pragma unroll
        for (int l = 0; l < 2; l++) {
            int m = fa_m + l * 64;
            As[buf][m][fa_s0 + 0] = f2tf(aReg[l].x);
            As[buf][m][fa_s0 + 2] = f2tf(aReg[l].y);
            As[buf][m][fa_s0 + 4] = f2tf(aReg[l].z);
            As[buf][m][fa_s0 + 6] = f2tf(aReg[l].w);
        }
        #pragma unroll
        for (int l = 0; l < 2; l++) {
            int idx = tid + l * 256;
            int kr = idx >> 5;
            int c = (idx & 31) * 4;
            *(uint4*)&Bs[buf][kr][c] =
                make_uint4(f2tf(bReg[l].x), f2tf(bReg[l].y), f2tf(bReg[l].z), f2tf(bReg[l].w));
        }
    };

    auto MMA_chunk = [&](auto bufc) {
        constexpr int buf = decltype(bufc)::value;
        #pragma unroll
        for (int kk = 0; kk < 16; kk += 8) {
            uint32_t afr[4][4], bfr[4][2];
            #pragma unroll
            for (int mt = 0; mt < 4; mt++) {
                int mb = warp_m * 64 + mt * 16;
                uint2 lo = *(const uint2*)&As[buf][mb + r][kk + 2 * cq];
                uint2 hi = *(const uint2*)&As[buf][mb + r + 8][kk + 2 * cq];
                afr[mt][0] = lo.x; afr[mt][1] = hi.x;
                afr[mt][2] = lo.y; afr[mt][3] = hi.y;
            }
            #pragma unroll
            for (int nt = 0; nt < 4; nt++) {
                int nb = warp_n * 32 + nt * 8;
                bfr[nt][0] = Bs[buf][kk + cq][nb + r];
                bfr[nt][1] = Bs[buf][kk + cq + 4][nb + r];
            }
            #pragma unroll
            for (int mt = 0; mt < 4; mt++)
                #pragma unroll
                for (int nt = 0; nt < 4; nt++)
                    mma_tf32(acc[mt][nt], afr[mt], bfr[nt]);
        }
    };

    std::integral_constant<int, 0> B0;
    std::integral_constant<int, 1> B1;

    const int NC = KT / 16;     // even
    LDG_chunk(0);
    STS_chunk(B0);
    __syncthreads();
    #pragma unroll 1
    for (int c = 0; c < NC; c += 2) {
        LDG_chunk((c + 1) * 16);
        MMA_chunk(B0);
        STS_chunk(B1);
        __syncthreads();
        if (c + 2 < NC) LDG_chunk((c + 2) * 16);
        MMA_chunk(B1);
        if (c + 2 < NC) {
            STS_chunk(B0);
            __syncthreads();
        }
    }

    float* C = (CMODE == 0) ? Cp : g_h;
    #pragma unroll
    for (int mt = 0; mt < 4; mt++) {
        int mA = m0 + warp_m * 64 + mt * 16 + r;
        #pragma unroll
        for (int nt = 0; nt < 4; nt++) {
            int n = n0 + warp_n * 32 + nt * 8 + 2 * cq;
            if (mA < M) {
                float2 v = make_float2(acc[mt][nt][0], acc[mt][nt][1]);
                if (HAS_BIAS) { v.x += bias[n]; v.y += bias[n + 1]; }
                if (ADD_C) {
                    float2 o = *(const float2*)&C[(size_t)mA * N + n];
                    v.x += o.x; v.y += o.y;
                }
                *(float2*)&C[(size_t)mA * N + n] = v;
            }
            int mB = mA + 8;
            if (mB < M) {
                float2 v = make_float2(acc[mt][nt][2], acc[mt][nt][3]);
                if (HAS_BIAS) { v.x += bias[n]; v.y += bias[n + 1]; }
                if (ADD_C) {
                    float2 o = *(const float2*)&C[(size_t)mB * N + n];
                    v.x += o.x; v.y += o.y;
                }
                *(float2*)&C[(size_t)mB * N + n] = v;
            }
        }
    }
}

// ---------------- launch ----------------
extern "C" void kernel_launch(void* const* d_in, const int* in_sizes, int n_in,
                              void* d_out, int out_size)
{
    const float* x      = (const float*)d_in[0];
    const int*   ei     = (const int*)d_in[1];    // int64 in reference -> delivered as int32
    const int*   et     = (const int*)d_in[2];
    const float* norm   = (const float*)d_in[3];
    const float* basis  = (const float*)d_in[4];
    const float* comp   = (const float*)d_in[5];
    const float* root   = (const float*)d_in[6];
    const float* bias1  = (const float*)d_in[7];
    const float* w_rel  = (const float*)d_in[8];
    const float* b_rel  = (const float*)d_in[9];
    const float* w_root = (const float*)d_in[10];
    float* out = (float*)d_out;

    const int MBLK = (N_NODES + 127) / 128;   // 391

    static cudaStream_t s_side = nullptr;
    static cudaEvent_t ev_fork = nullptr, ev_join = nullptr;
    if (s_side == nullptr) {
        cudaStreamCreateWithFlags(&s_side, cudaStreamNonBlocking);
        cudaEventCreateWithFlags(&ev_fork, cudaEventDisableTiming);
        cudaEventCreateWithFlags(&ev_join, cudaEventDisableTiming);
    }

    // ---- fork: weights on side stream, CSR build on main (critical path) ----
    cudaEventRecord(ev_fork, 0);
    cudaStreamWaitEvent(s_side, ev_fork, 0);
    k_W<<<(RELS * DIM * DIM + 255) / 256, 256, 0, s_side>>>(basis, comp);
    cudaEventRecord(ev_join, s_side);

    k_zero2<<<(N_NODES * RELS + 255) / 256, 256>>>();
    k_hist2<<<(N_EDGES + 255) / 256, 256>>>(ei, et);
    k_scan_p1<<<SCAN_G, SCAN_B>>>();
    k_scan_p2<<<1, 128>>>();
    k_scan_p3<<<SCAN_G, SCAN_B>>>();
    k_scatter2<<<(N_EDGES + 255) / 256, 256>>>(ei, et, norm);

    // per-relation aggregation of raw x (x is L2-resident)
    k_aggX<<<(N_NODES + 7) / 8, 256>>>(x);

    cudaStreamWaitEvent(0, ev_join, 0);
    // layer 1 in ONE concat GEMM: h = [aggX | x] @ [W2cat; root] + bias1, K=1152
    {
        dim3 grid(1, MBLK);
        k_gemm_tc<1152, 4, 3, 2, false, true><<<grid, 256>>>(x, nullptr, root, nullptr,
                                                             N_NODES, DIM, bias1);
    }
    // layer-2 aggregation -> g_agg2 (g_h is L2-resident)
    k_agg2<<<(N_NODES + 7) / 8, 256>>>();
    // out = [agg2, h] @ [w_rel; w_root] + b_rel   (fused K=256)
    {
        dim3 grid(1, MBLK);
        k_gemm_tc<256, 3, 2, 0, false, true><<<grid, 256>>>(nullptr, w_rel, w_root, out,
                                                            N_NODES, DIM, b_rel);
    }
}